// round 1
// baseline (speedup 1.0000x reference)
#include <cuda_runtime.h>
#include <cuda_bf16.h>

#define L_TOK 4096
#define DIMC 576
#define QKVD 1728
#define NHEADS 8
#define DH 72
#define OUTC 128
#define KT 32

// Scratch (allocation-free: __device__ globals)
__device__ float g_x[L_TOK * DIMC];      // unfold output  [L,576]
__device__ float g_qkv[L_TOK * QKVD];    // qkv            [L,1728]
__device__ float g_attn[L_TOK * DIMC];   // attention out  [L,576]
__device__ float g_x2[L_TOK * DIMC];     // attn+resid     [L,576]

// ---------------------------------------------------------------------------
// Unfold 3x3 stride2 pad1: x[l, c*9 + ki*3 + kj] = fea[c, 2*ho+ki-1, 2*wo+kj-1]
// ---------------------------------------------------------------------------
__global__ void unfold_kernel(const float* __restrict__ fea, float* __restrict__ x) {
    int idx = blockIdx.x * blockDim.x + threadIdx.x;
    if (idx >= L_TOK * DIMC) return;
    int l = idx / DIMC, d = idx - l * DIMC;
    int c = d / 9, r = d - c * 9;
    int ki = r / 3, kj = r - ki * 3;
    int ho = l >> 6, wo = l & 63;
    int h = 2 * ho + ki - 1;
    int w = 2 * wo + kj - 1;
    float v = 0.f;
    if (h >= 0 && h < 128 && w >= 0 && w < 128)
        v = fea[c * 16384 + h * 128 + w];
    x[idx] = v;
}

// ---------------------------------------------------------------------------
// Tiled SGEMM: C[M,N] = A[M,K] @ B[K,N] (+epilogue).
// BM=128 BN=64 BK=16, 256 threads, 8x4 microtile. All dims divide exactly.
// MODE 0: +bias            -> C[m*N+n]
// MODE 1: +bias +residual  -> C[m*N+n]
// MODE 2: silu, transposed -> C[n*M+m]     (B accessed transposed when TRANSB)
// ---------------------------------------------------------------------------
template <int MODE, bool TRANSB>
__global__ void __launch_bounds__(256) sgemm_kernel(
    const float* __restrict__ A, const float* __restrict__ B,
    const float* __restrict__ bias, const float* __restrict__ resid,
    float* __restrict__ C, int M, int N, int K)
{
    __shared__ __align__(16) float As[16 * 128];
    __shared__ __align__(16) float Bs[16 * 64];

    const int tid = threadIdx.x;
    const int bm = blockIdx.y * 128;
    const int bn = blockIdx.x * 64;
    const int tr = tid >> 4;      // 0..15, rows tr*8..tr*8+7
    const int tc = tid & 15;      // 0..15, cols tc*4..tc*4+3

    // A-load mapping: 128 rows x 16 cols, each thread 8 floats (2x float4)
    const int a_m = tid >> 1;
    const int a_k = (tid & 1) * 8;
    // B-load mapping
    int b_k, b_n;
    if (TRANSB) { b_n = tid >> 2; b_k = (tid & 3) * 4; }  // read along K of B[n*K+k]
    else        { b_k = tid >> 4; b_n = (tid & 15) * 4; }

    float acc[8][4];
#pragma unroll
    for (int i = 0; i < 8; i++)
#pragma unroll
        for (int j = 0; j < 4; j++) acc[i][j] = 0.f;

    for (int k0 = 0; k0 < K; k0 += 16) {
        // --- load A tile (transposed into smem) ---
        const float* Ap = A + (long)(bm + a_m) * K + k0 + a_k;
        float4 av0 = *(const float4*)(Ap);
        float4 av1 = *(const float4*)(Ap + 4);
        As[(a_k + 0) * 128 + a_m] = av0.x;
        As[(a_k + 1) * 128 + a_m] = av0.y;
        As[(a_k + 2) * 128 + a_m] = av0.z;
        As[(a_k + 3) * 128 + a_m] = av0.w;
        As[(a_k + 4) * 128 + a_m] = av1.x;
        As[(a_k + 5) * 128 + a_m] = av1.y;
        As[(a_k + 6) * 128 + a_m] = av1.z;
        As[(a_k + 7) * 128 + a_m] = av1.w;
        // --- load B tile ---
        if (TRANSB) {
            float4 bv = *(const float4*)(B + (long)(bn + b_n) * K + k0 + b_k);
            Bs[(b_k + 0) * 64 + b_n] = bv.x;
            Bs[(b_k + 1) * 64 + b_n] = bv.y;
            Bs[(b_k + 2) * 64 + b_n] = bv.z;
            Bs[(b_k + 3) * 64 + b_n] = bv.w;
        } else {
            *(float4*)&Bs[b_k * 64 + b_n] =
                *(const float4*)(B + (long)(k0 + b_k) * N + bn + b_n);
        }
        __syncthreads();

#pragma unroll
        for (int kk = 0; kk < 16; kk++) {
            float4 a0 = *(float4*)&As[kk * 128 + tr * 8];
            float4 a1 = *(float4*)&As[kk * 128 + tr * 8 + 4];
            float4 b  = *(float4*)&Bs[kk * 64 + tc * 4];
            float av[8] = {a0.x, a0.y, a0.z, a0.w, a1.x, a1.y, a1.z, a1.w};
            float bv[4] = {b.x, b.y, b.z, b.w};
#pragma unroll
            for (int i = 0; i < 8; i++)
#pragma unroll
                for (int j = 0; j < 4; j++) acc[i][j] += av[i] * bv[j];
        }
        __syncthreads();
    }

    // --- epilogue ---
#pragma unroll
    for (int i = 0; i < 8; i++) {
        int m = bm + tr * 8 + i;
#pragma unroll
        for (int j = 0; j < 4; j++) {
            int n = bn + tc * 4 + j;
            float v = acc[i][j];
            if (MODE == 0) {
                C[(long)m * N + n] = v + bias[n];
            } else if (MODE == 1) {
                C[(long)m * N + n] = v + bias[n] + resid[(long)m * N + n];
            } else {  // MODE 2: silu + transposed store [N, M]
                float s = v / (1.f + __expf(-v));
                C[(long)n * M + m] = s;
            }
        }
    }
}

// ---------------------------------------------------------------------------
// Flash attention, fp32. Grid: (L/128 q-tiles, heads). 128 threads, 1 thr = 1 query.
// q,k,v live in g_qkv at offsets 0/576/1152 within each row of 1728.
// ---------------------------------------------------------------------------
__global__ void __launch_bounds__(128) flash_kernel(
    const float* __restrict__ qkv, float* __restrict__ attn_out)
{
    __shared__ __align__(16) float ks[KT * DH];
    __shared__ __align__(16) float vs[KT * DH];
    __shared__ float ss[KT * 128];

    const int tid = threadIdx.x;
    const int h = blockIdx.y;
    const int q_l = blockIdx.x * 128 + tid;
    const float scale = rsqrtf((float)DH);

    float q[DH];
    const float* qp = qkv + (long)q_l * QKVD + h * DH;
#pragma unroll
    for (int d = 0; d < DH; d++) q[d] = qp[d] * scale;

    float o[DH];
#pragma unroll
    for (int d = 0; d < DH; d++) o[d] = 0.f;
    float m = -1e30f, lsum = 0.f;

    for (int kt = 0; kt < L_TOK / KT; kt++) {
        __syncthreads();
        const float* kbase = qkv + (long)(kt * KT) * QKVD + DIMC + h * DH;
        const float* vbase = kbase + DIMC;
        for (int i = tid; i < KT * (DH / 4); i += 128) {
            int j = i / (DH / 4), d4 = i - j * (DH / 4);
            *(float4*)&ks[j * DH + d4 * 4] = *(const float4*)(kbase + (long)j * QKVD + d4 * 4);
            *(float4*)&vs[j * DH + d4 * 4] = *(const float4*)(vbase + (long)j * QKVD + d4 * 4);
        }
        __syncthreads();

        // scores for this tile
        float tmax = -1e30f;
#pragma unroll 4
        for (int j = 0; j < KT; j++) {
            float s = 0.f;
#pragma unroll
            for (int d4 = 0; d4 < DH / 4; d4++) {
                float4 kv = *(float4*)&ks[j * DH + d4 * 4];
                s += q[4 * d4 + 0] * kv.x + q[4 * d4 + 1] * kv.y
                   + q[4 * d4 + 2] * kv.z + q[4 * d4 + 3] * kv.w;
            }
            ss[j * 128 + tid] = s;
            tmax = fmaxf(tmax, s);
        }

        float mnew = fmaxf(m, tmax);
        float corr = __expf(m - mnew);
        lsum *= corr;
#pragma unroll
        for (int d = 0; d < DH; d++) o[d] *= corr;

#pragma unroll 2
        for (int j = 0; j < KT; j++) {
            float p = __expf(ss[j * 128 + tid] - mnew);
            lsum += p;
#pragma unroll
            for (int d4 = 0; d4 < DH / 4; d4++) {
                float4 vv = *(float4*)&vs[j * DH + d4 * 4];
                o[4 * d4 + 0] += p * vv.x;
                o[4 * d4 + 1] += p * vv.y;
                o[4 * d4 + 2] += p * vv.z;
                o[4 * d4 + 3] += p * vv.w;
            }
        }
        m = mnew;
    }

    float inv = 1.f / lsum;
    float* op = attn_out + (long)q_l * DIMC + h * DH;
#pragma unroll
    for (int d = 0; d < DH; d++) op[d] = o[d] * inv;
}

// ---------------------------------------------------------------------------
extern "C" void kernel_launch(void* const* d_in, const int* in_sizes, int n_in,
                              void* d_out, int out_size)
{
    const float* fea    = (const float*)d_in[0];  // [1,64,128,128]
    const float* w_qkv  = (const float*)d_in[1];  // [576,1728]
    const float* b_qkv  = (const float*)d_in[2];  // [1728]
    const float* w_out  = (const float*)d_in[3];  // [576,576]
    const float* b_out  = (const float*)d_in[4];  // [576]
    const float* conv_w = (const float*)d_in[5];  // [128,64,3,3] = [128,576]
    float* out = (float*)d_out;                   // [1,128,64,64]

    float* x    = nullptr; cudaGetSymbolAddress((void**)&x,    g_x);
    float* qkv  = nullptr; cudaGetSymbolAddress((void**)&qkv,  g_qkv);
    float* attn = nullptr; cudaGetSymbolAddress((void**)&attn, g_attn);
    float* x2   = nullptr; cudaGetSymbolAddress((void**)&x2,   g_x2);

    // 1) unfold
    unfold_kernel<<<(L_TOK * DIMC + 255) / 256, 256>>>(fea, x);

    // 2) qkv = x @ w_qkv + b_qkv   [4096,1728]
    sgemm_kernel<0, false><<<dim3(QKVD / 64, L_TOK / 128), 256>>>(
        x, w_qkv, b_qkv, nullptr, qkv, L_TOK, QKVD, DIMC);

    // 3) flash attention -> attn [4096,576]
    flash_kernel<<<dim3(L_TOK / 128, NHEADS), 128>>>(qkv, attn);

    // 4) x2 = attn @ w_out + b_out + x
    sgemm_kernel<1, false><<<dim3(DIMC / 64, L_TOK / 128), 256>>>(
        attn, w_out, b_out, x, x2, L_TOK, DIMC, DIMC);

    // 5) out[oc,l] = silu( x2 @ conv_w^T )
    sgemm_kernel<2, true><<<dim3(OUTC / 64, L_TOK / 128), 256>>>(
        x2, conv_w, nullptr, nullptr, out, L_TOK, OUTC, DIMC);
}

// round 2
// speedup vs baseline: 1.5411x; 1.5411x over previous
#include <cuda_runtime.h>
#include <cuda_bf16.h>
#include <cstdint>

#define L_TOK 4096
#define DIMC 576
#define QKVD 1728
#define NHEADS 8
#define DH 72
#define OUTC 128

// Scratch (allocation-free: __device__ globals)
__device__ float g_x[L_TOK * DIMC];      // unfold output  [L,576]
__device__ float g_qkv[L_TOK * QKVD];    // qkv            [L,1728]
__device__ float g_attn[L_TOK * DIMC];   // attention out  [L,576]
__device__ float g_x2[L_TOK * DIMC];     // attn+resid     [L,576]

// ---------------------------------------------------------------------------
// helpers
// ---------------------------------------------------------------------------
__device__ __forceinline__ uint32_t f2tf32(float x) {
    uint32_t r;
    asm("cvt.rna.tf32.f32 %0, %1;" : "=r"(r) : "f"(x));
    return r;
}

__device__ __forceinline__ void mma_tf32(float d[4],
                                         const uint32_t a[4],
                                         uint32_t b0, uint32_t b1) {
    asm volatile(
        "mma.sync.aligned.m16n8k8.row.col.f32.tf32.tf32.f32 "
        "{%0,%1,%2,%3}, {%4,%5,%6,%7}, {%8,%9}, {%0,%1,%2,%3};\n"
        : "+f"(d[0]), "+f"(d[1]), "+f"(d[2]), "+f"(d[3])
        : "r"(a[0]), "r"(a[1]), "r"(a[2]), "r"(a[3]), "r"(b0), "r"(b1));
}

// ---------------------------------------------------------------------------
// Unfold 3x3 stride2 pad1
// ---------------------------------------------------------------------------
__global__ void unfold_kernel(const float* __restrict__ fea, float* __restrict__ x) {
    int idx = blockIdx.x * blockDim.x + threadIdx.x;
    if (idx >= L_TOK * DIMC) return;
    int l = idx / DIMC, d = idx - l * DIMC;
    int c = d / 9, r = d - c * 9;
    int ki = r / 3, kj = r - ki * 3;
    int ho = l >> 6, wo = l & 63;
    int h = 2 * ho + ki - 1;
    int w = 2 * wo + kj - 1;
    float v = 0.f;
    if (h >= 0 && h < 128 && w >= 0 && w < 128)
        v = fea[c * 16384 + h * 128 + w];
    x[idx] = v;
}

// ---------------------------------------------------------------------------
// Tiled SGEMM (fp32, unchanged from R1)
// ---------------------------------------------------------------------------
template <int MODE, bool TRANSB>
__global__ void __launch_bounds__(256) sgemm_kernel(
    const float* __restrict__ A, const float* __restrict__ B,
    const float* __restrict__ bias, const float* __restrict__ resid,
    float* __restrict__ C, int M, int N, int K)
{
    __shared__ __align__(16) float As[16 * 128];
    __shared__ __align__(16) float Bs[16 * 64];

    const int tid = threadIdx.x;
    const int bm = blockIdx.y * 128;
    const int bn = blockIdx.x * 64;
    const int tr = tid >> 4;
    const int tc = tid & 15;

    const int a_m = tid >> 1;
    const int a_k = (tid & 1) * 8;
    int b_k, b_n;
    if (TRANSB) { b_n = tid >> 2; b_k = (tid & 3) * 4; }
    else        { b_k = tid >> 4; b_n = (tid & 15) * 4; }

    float acc[8][4];
#pragma unroll
    for (int i = 0; i < 8; i++)
#pragma unroll
        for (int j = 0; j < 4; j++) acc[i][j] = 0.f;

    for (int k0 = 0; k0 < K; k0 += 16) {
        const float* Ap = A + (long)(bm + a_m) * K + k0 + a_k;
        float4 av0 = *(const float4*)(Ap);
        float4 av1 = *(const float4*)(Ap + 4);
        As[(a_k + 0) * 128 + a_m] = av0.x;
        As[(a_k + 1) * 128 + a_m] = av0.y;
        As[(a_k + 2) * 128 + a_m] = av0.z;
        As[(a_k + 3) * 128 + a_m] = av0.w;
        As[(a_k + 4) * 128 + a_m] = av1.x;
        As[(a_k + 5) * 128 + a_m] = av1.y;
        As[(a_k + 6) * 128 + a_m] = av1.z;
        As[(a_k + 7) * 128 + a_m] = av1.w;
        if (TRANSB) {
            float4 bv = *(const float4*)(B + (long)(bn + b_n) * K + k0 + b_k);
            Bs[(b_k + 0) * 64 + b_n] = bv.x;
            Bs[(b_k + 1) * 64 + b_n] = bv.y;
            Bs[(b_k + 2) * 64 + b_n] = bv.z;
            Bs[(b_k + 3) * 64 + b_n] = bv.w;
        } else {
            *(float4*)&Bs[b_k * 64 + b_n] =
                *(const float4*)(B + (long)(k0 + b_k) * N + bn + b_n);
        }
        __syncthreads();

#pragma unroll
        for (int kk = 0; kk < 16; kk++) {
            float4 a0 = *(float4*)&As[kk * 128 + tr * 8];
            float4 a1 = *(float4*)&As[kk * 128 + tr * 8 + 4];
            float4 b  = *(float4*)&Bs[kk * 64 + tc * 4];
            float av[8] = {a0.x, a0.y, a0.z, a0.w, a1.x, a1.y, a1.z, a1.w};
            float bv[4] = {b.x, b.y, b.z, b.w};
#pragma unroll
            for (int i = 0; i < 8; i++)
#pragma unroll
                for (int j = 0; j < 4; j++) acc[i][j] += av[i] * bv[j];
        }
        __syncthreads();
    }

#pragma unroll
    for (int i = 0; i < 8; i++) {
        int m = bm + tr * 8 + i;
#pragma unroll
        for (int j = 0; j < 4; j++) {
            int n = bn + tc * 4 + j;
            float v = acc[i][j];
            if (MODE == 0) {
                C[(long)m * N + n] = v + bias[n];
            } else if (MODE == 1) {
                C[(long)m * N + n] = v + bias[n] + resid[(long)m * N + n];
            } else {
                float s = v / (1.f + __expf(-v));
                C[(long)n * M + m] = s;
            }
        }
    }
}

// ---------------------------------------------------------------------------
// Flash attention, tf32 tensor cores.
// Grid: (64 q-tiles, 8 heads). 128 threads = 4 warps; warp w owns query rows
// [w*16, w*16+16). KV tile = 64 keys.
//
// SMEM: Ks[64][76] tf32, Vs[64][76] tf32 (stride 76 -> conflict-free B frags).
// P (per-warp 16x64, stride 68) aliases the Ks region after S is consumed.
// ---------------------------------------------------------------------------
#define KSTRIDE 76
#define PSTRIDE 68
#define KTILE 64

__global__ void __launch_bounds__(128, 3) flash_tc_kernel(
    const float* __restrict__ qkv, float* __restrict__ attn_out)
{
    __shared__ uint32_t Ks[KTILE * KSTRIDE];   // also aliased as P
    __shared__ uint32_t Vs[KTILE * KSTRIDE];

    const int tid  = threadIdx.x;
    const int w    = tid >> 5;
    const int lane = tid & 31;
    const int g    = lane >> 2;   // group id (row within 8)
    const int t    = lane & 3;    // thread in group
    const int h    = blockIdx.y;
    const int q0   = blockIdx.x * 64;
    const float scale = rsqrtf((float)DH);

    // Q fragments for this warp: rows q0+w*16+{g, g+8}, all 9 k-steps
    uint32_t qa[9][4];
    {
        const float* qb = qkv + (long)(q0 + w * 16) * QKVD + h * DH;
#pragma unroll
        for (int ks = 0; ks < 9; ks++) {
            qa[ks][0] = f2tf32(qb[(long)g       * QKVD + ks * 8 + t]     * scale);
            qa[ks][1] = f2tf32(qb[(long)(g + 8) * QKVD + ks * 8 + t]     * scale);
            qa[ks][2] = f2tf32(qb[(long)g       * QKVD + ks * 8 + t + 4] * scale);
            qa[ks][3] = f2tf32(qb[(long)(g + 8) * QKVD + ks * 8 + t + 4] * scale);
        }
    }

    float o[9][4];
#pragma unroll
    for (int n = 0; n < 9; n++)
#pragma unroll
        for (int j = 0; j < 4; j++) o[n][j] = 0.f;
    float m0 = -1e30f, m1 = -1e30f, l0 = 0.f, l1 = 0.f;

    uint32_t* Pw = Ks + w * (16 * PSTRIDE);   // this warp's P region (aliases Ks)

    for (int kt = 0; kt < L_TOK / KTILE; kt++) {
        __syncthreads();   // prev PV (P + Vs reads) done -> safe to reload K,V

        // load K,V tiles (tf32-converted). 64 rows x 18 float4 each.
        {
            const float* kb = qkv + (long)(kt * KTILE) * QKVD + DIMC + h * DH;
#pragma unroll
            for (int it = 0; it < 9; it++) {
                int idx = tid + it * 128;           // 0..1151
                int row = idx / 18, c = idx % 18;
                const float* src = kb + (long)row * QKVD + c * 4;
                float4 kv = *(const float4*)src;
                uint32_t* dst = &Ks[row * KSTRIDE + c * 4];
                dst[0] = f2tf32(kv.x); dst[1] = f2tf32(kv.y);
                dst[2] = f2tf32(kv.z); dst[3] = f2tf32(kv.w);
                float4 vv = *(const float4*)(src + DIMC);
                uint32_t* dstv = &Vs[row * KSTRIDE + c * 4];
                dstv[0] = f2tf32(vv.x); dstv[1] = f2tf32(vv.y);
                dstv[2] = f2tf32(vv.z); dstv[3] = f2tf32(vv.w);
            }
        }
        __syncthreads();

        // --- S = Q @ K^T  (16 x 64 per warp) ---
        float s[8][4];
#pragma unroll
        for (int n = 0; n < 8; n++)
#pragma unroll
            for (int j = 0; j < 4; j++) s[n][j] = 0.f;

#pragma unroll
        for (int ks = 0; ks < 9; ks++) {
#pragma unroll
            for (int nn = 0; nn < 8; nn++) {
                uint32_t b0 = Ks[(nn * 8 + g) * KSTRIDE + ks * 8 + t];
                uint32_t b1 = Ks[(nn * 8 + g) * KSTRIDE + ks * 8 + t + 4];
                mma_tf32(s[nn], qa[ks], b0, b1);
            }
        }

        // --- online softmax ---
        float rmax0 = -1e30f, rmax1 = -1e30f;
#pragma unroll
        for (int nn = 0; nn < 8; nn++) {
            rmax0 = fmaxf(rmax0, fmaxf(s[nn][0], s[nn][1]));
            rmax1 = fmaxf(rmax1, fmaxf(s[nn][2], s[nn][3]));
        }
        rmax0 = fmaxf(rmax0, __shfl_xor_sync(0xffffffffu, rmax0, 1));
        rmax0 = fmaxf(rmax0, __shfl_xor_sync(0xffffffffu, rmax0, 2));
        rmax1 = fmaxf(rmax1, __shfl_xor_sync(0xffffffffu, rmax1, 1));
        rmax1 = fmaxf(rmax1, __shfl_xor_sync(0xffffffffu, rmax1, 2));

        float mn0 = fmaxf(m0, rmax0), mn1 = fmaxf(m1, rmax1);
        float corr0 = __expf(m0 - mn0), corr1 = __expf(m1 - mn1);
        m0 = mn0; m1 = mn1;

        __syncthreads();   // everyone done reading Ks -> safe to write P over it

        float rs0 = 0.f, rs1 = 0.f;
#pragma unroll
        for (int nn = 0; nn < 8; nn++) {
            float p0 = __expf(s[nn][0] - mn0);
            float p1 = __expf(s[nn][1] - mn0);
            float p2 = __expf(s[nn][2] - mn1);
            float p3 = __expf(s[nn][3] - mn1);
            rs0 += p0 + p1; rs1 += p2 + p3;
            Pw[g       * PSTRIDE + nn * 8 + 2 * t]     = f2tf32(p0);
            Pw[g       * PSTRIDE + nn * 8 + 2 * t + 1] = f2tf32(p1);
            Pw[(g + 8) * PSTRIDE + nn * 8 + 2 * t]     = f2tf32(p2);
            Pw[(g + 8) * PSTRIDE + nn * 8 + 2 * t + 1] = f2tf32(p3);
        }
        rs0 += __shfl_xor_sync(0xffffffffu, rs0, 1);
        rs0 += __shfl_xor_sync(0xffffffffu, rs0, 2);
        rs1 += __shfl_xor_sync(0xffffffffu, rs1, 1);
        rs1 += __shfl_xor_sync(0xffffffffu, rs1, 2);
        l0 = l0 * corr0 + rs0;
        l1 = l1 * corr1 + rs1;

#pragma unroll
        for (int n = 0; n < 9; n++) {
            o[n][0] *= corr0; o[n][1] *= corr0;
            o[n][2] *= corr1; o[n][3] *= corr1;
        }

        __syncwarp();

        // --- O += P @ V  (16 x 72 per warp) ---
#pragma unroll
        for (int kk = 0; kk < 8; kk++) {
            uint32_t a[4];
            a[0] = Pw[g       * PSTRIDE + kk * 8 + t];
            a[1] = Pw[(g + 8) * PSTRIDE + kk * 8 + t];
            a[2] = Pw[g       * PSTRIDE + kk * 8 + t + 4];
            a[3] = Pw[(g + 8) * PSTRIDE + kk * 8 + t + 4];
#pragma unroll
            for (int nn = 0; nn < 9; nn++) {
                uint32_t b0 = Vs[(kk * 8 + t)     * KSTRIDE + nn * 8 + g];
                uint32_t b1 = Vs[(kk * 8 + t + 4) * KSTRIDE + nn * 8 + g];
                mma_tf32(o[nn], a, b0, b1);
            }
        }
    }

    // epilogue: normalize and store
    float inv0 = 1.f / l0, inv1 = 1.f / l1;
    float* ob = attn_out + (long)(q0 + w * 16) * DIMC + h * DH;
#pragma unroll
    for (int nn = 0; nn < 9; nn++) {
        float2 v0 = make_float2(o[nn][0] * inv0, o[nn][1] * inv0);
        float2 v1 = make_float2(o[nn][2] * inv1, o[nn][3] * inv1);
        *(float2*)(ob + (long)g       * DIMC + nn * 8 + 2 * t) = v0;
        *(float2*)(ob + (long)(g + 8) * DIMC + nn * 8 + 2 * t) = v1;
    }
}

// ---------------------------------------------------------------------------
extern "C" void kernel_launch(void* const* d_in, const int* in_sizes, int n_in,
                              void* d_out, int out_size)
{
    const float* fea    = (const float*)d_in[0];
    const float* w_qkv  = (const float*)d_in[1];
    const float* b_qkv  = (const float*)d_in[2];
    const float* w_out  = (const float*)d_in[3];
    const float* b_out  = (const float*)d_in[4];
    const float* conv_w = (const float*)d_in[5];
    float* out = (float*)d_out;

    float* x    = nullptr; cudaGetSymbolAddress((void**)&x,    g_x);
    float* qkv  = nullptr; cudaGetSymbolAddress((void**)&qkv,  g_qkv);
    float* attn = nullptr; cudaGetSymbolAddress((void**)&attn, g_attn);
    float* x2   = nullptr; cudaGetSymbolAddress((void**)&x2,   g_x2);

    // 1) unfold
    unfold_kernel<<<(L_TOK * DIMC + 255) / 256, 256>>>(fea, x);

    // 2) qkv = x @ w_qkv + b_qkv
    sgemm_kernel<0, false><<<dim3(QKVD / 64, L_TOK / 128), 256>>>(
        x, w_qkv, b_qkv, nullptr, qkv, L_TOK, QKVD, DIMC);

    // 3) flash attention (tf32 tensor cores)
    flash_tc_kernel<<<dim3(L_TOK / 64, NHEADS), 128>>>(qkv, attn);

    // 4) x2 = attn @ w_out + b_out + x
    sgemm_kernel<1, false><<<dim3(DIMC / 64, L_TOK / 128), 256>>>(
        attn, w_out, b_out, x, x2, L_TOK, DIMC, DIMC);

    // 5) out[oc,l] = silu( x2 @ conv_w^T )
    sgemm_kernel<2, true><<<dim3(OUTC / 64, L_TOK / 128), 256>>>(
        x2, conv_w, nullptr, nullptr, out, L_TOK, OUTC, DIMC);
}

// round 3
// speedup vs baseline: 3.3658x; 2.1841x over previous
#include <cuda_runtime.h>
#include <cuda_bf16.h>
#include <cstdint>

#define L_TOK 4096
#define DIMC 576
#define QKVD 1728
#define NHEADS 8
#define DH 72
#define OUTC 128

// Scratch (allocation-free: __device__ globals)
__device__ float g_x[L_TOK * DIMC];      // unfold output  [L,576]
__device__ float g_qkv[L_TOK * QKVD];    // qkv            [L,1728]
__device__ float g_attn[L_TOK * DIMC];   // attention out  [L,576]
__device__ float g_x2[L_TOK * DIMC];     // attn+resid     [L,576]

// ---------------------------------------------------------------------------
// helpers
// ---------------------------------------------------------------------------
__device__ __forceinline__ uint32_t f2tf32(float x) {
    uint32_t r;
    asm("cvt.rna.tf32.f32 %0, %1;" : "=r"(r) : "f"(x));
    return r;
}

__device__ __forceinline__ void mma_tf32(float d[4],
                                         const uint32_t a[4],
                                         uint32_t b0, uint32_t b1) {
    asm volatile(
        "mma.sync.aligned.m16n8k8.row.col.f32.tf32.tf32.f32 "
        "{%0,%1,%2,%3}, {%4,%5,%6,%7}, {%8,%9}, {%0,%1,%2,%3};\n"
        : "+f"(d[0]), "+f"(d[1]), "+f"(d[2]), "+f"(d[3])
        : "r"(a[0]), "r"(a[1]), "r"(a[2]), "r"(a[3]), "r"(b0), "r"(b1));
}

// ---------------------------------------------------------------------------
// Unfold 3x3 stride2 pad1
// ---------------------------------------------------------------------------
__global__ void unfold_kernel(const float* __restrict__ fea, float* __restrict__ x) {
    int idx = blockIdx.x * blockDim.x + threadIdx.x;
    if (idx >= L_TOK * DIMC) return;
    int l = idx / DIMC, d = idx - l * DIMC;
    int c = d / 9, r = d - c * 9;
    int ki = r / 3, kj = r - ki * 3;
    int ho = l >> 6, wo = l & 63;
    int h = 2 * ho + ki - 1;
    int w = 2 * wo + kj - 1;
    float v = 0.f;
    if (h >= 0 && h < 128 && w >= 0 && w < 128)
        v = fea[c * 16384 + h * 128 + w];
    x[idx] = v;
}

// ---------------------------------------------------------------------------
// tf32 tensor-core GEMM: C[M,N] = A[M,K] @ B[K,N] (+epilogue)
// BM=128 BN=64 BK=16, 256 threads = 8 warps (4 m x 2 n), warp tile 32x32.
// As stride 20, Bs stride 72 (bank-conflict-free fragment reads).
// MODE 0: +bias ; MODE 1: +bias+resid ; MODE 2: silu + transposed store [N,M]
// ---------------------------------------------------------------------------
#define AST 20
#define BST 72

template <int MODE, bool TRANSB>
__global__ void __launch_bounds__(256) tf32_gemm_kernel(
    const float* __restrict__ A, const float* __restrict__ B,
    const float* __restrict__ bias, const float* __restrict__ resid,
    float* __restrict__ C, int M, int N, int K)
{
    __shared__ __align__(16) uint32_t As[128 * AST];
    __shared__ __align__(16) uint32_t Bs[16 * BST];

    const int tid  = threadIdx.x;
    const int lane = tid & 31;
    const int warp = tid >> 5;
    const int g = lane >> 2;
    const int t = lane & 3;
    const int wm = (warp >> 1) * 32;   // 0,32,64,96
    const int wn = (warp & 1) * 32;    // 0,32
    const int bm = blockIdx.y * 128;
    const int bn = blockIdx.x * 64;

    const int a_m = tid >> 1;
    const int a_k = (tid & 1) * 8;
    int b_k, b_n;
    if (TRANSB) { b_n = tid >> 2; b_k = (tid & 3) * 4; }
    else        { b_k = tid >> 4; b_n = (tid & 15) * 4; }

    float acc[2][4][4];
#pragma unroll
    for (int i = 0; i < 2; i++)
#pragma unroll
        for (int j = 0; j < 4; j++)
#pragma unroll
            for (int f = 0; f < 4; f++) acc[i][j][f] = 0.f;

    for (int k0 = 0; k0 < K; k0 += 16) {
        // stage A (cvt to tf32)
        {
            const float* Ap = A + (long)(bm + a_m) * K + k0 + a_k;
            float4 v0 = *(const float4*)(Ap);
            float4 v1 = *(const float4*)(Ap + 4);
            uint4 u0 = make_uint4(f2tf32(v0.x), f2tf32(v0.y), f2tf32(v0.z), f2tf32(v0.w));
            uint4 u1 = make_uint4(f2tf32(v1.x), f2tf32(v1.y), f2tf32(v1.z), f2tf32(v1.w));
            *(uint4*)&As[a_m * AST + a_k]     = u0;
            *(uint4*)&As[a_m * AST + a_k + 4] = u1;
        }
        // stage B
        if (TRANSB) {
            float4 bv = *(const float4*)(B + (long)(bn + b_n) * K + k0 + b_k);
            Bs[(b_k + 0) * BST + b_n] = f2tf32(bv.x);
            Bs[(b_k + 1) * BST + b_n] = f2tf32(bv.y);
            Bs[(b_k + 2) * BST + b_n] = f2tf32(bv.z);
            Bs[(b_k + 3) * BST + b_n] = f2tf32(bv.w);
        } else {
            float4 bv = *(const float4*)(B + (long)(k0 + b_k) * N + bn + b_n);
            uint4 u = make_uint4(f2tf32(bv.x), f2tf32(bv.y), f2tf32(bv.z), f2tf32(bv.w));
            *(uint4*)&Bs[b_k * BST + b_n] = u;
        }
        __syncthreads();

#pragma unroll
        for (int ks = 0; ks < 2; ks++) {
            uint32_t af[2][4];
#pragma unroll
            for (int i = 0; i < 2; i++) {
                int mb = wm + i * 16;
                af[i][0] = As[(mb + g)     * AST + ks * 8 + t];
                af[i][1] = As[(mb + g + 8) * AST + ks * 8 + t];
                af[i][2] = As[(mb + g)     * AST + ks * 8 + t + 4];
                af[i][3] = As[(mb + g + 8) * AST + ks * 8 + t + 4];
            }
#pragma unroll
            for (int j = 0; j < 4; j++) {
                uint32_t b0 = Bs[(ks * 8 + t)     * BST + wn + j * 8 + g];
                uint32_t b1 = Bs[(ks * 8 + t + 4) * BST + wn + j * 8 + g];
                mma_tf32(acc[0][j], af[0], b0, b1);
                mma_tf32(acc[1][j], af[1], b0, b1);
            }
        }
        __syncthreads();
    }

    // epilogue
#pragma unroll
    for (int i = 0; i < 2; i++) {
#pragma unroll
        for (int j = 0; j < 4; j++) {
            int m0 = bm + wm + i * 16 + g;
            int m1 = m0 + 8;
            int n  = bn + wn + j * 8 + 2 * t;
            if (MODE == 0) {
                float2 bb = *(const float2*)(bias + n);
                *(float2*)(C + (long)m0 * N + n) =
                    make_float2(acc[i][j][0] + bb.x, acc[i][j][1] + bb.y);
                *(float2*)(C + (long)m1 * N + n) =
                    make_float2(acc[i][j][2] + bb.x, acc[i][j][3] + bb.y);
            } else if (MODE == 1) {
                float2 bb = *(const float2*)(bias + n);
                float2 r0 = *(const float2*)(resid + (long)m0 * N + n);
                float2 r1 = *(const float2*)(resid + (long)m1 * N + n);
                *(float2*)(C + (long)m0 * N + n) =
                    make_float2(acc[i][j][0] + bb.x + r0.x, acc[i][j][1] + bb.y + r0.y);
                *(float2*)(C + (long)m1 * N + n) =
                    make_float2(acc[i][j][2] + bb.x + r1.x, acc[i][j][3] + bb.y + r1.y);
            } else {
                float v0 = acc[i][j][0], v1 = acc[i][j][1];
                float v2 = acc[i][j][2], v3 = acc[i][j][3];
                C[(long)n * M + m0]       = v0 / (1.f + __expf(-v0));
                C[(long)(n + 1) * M + m0] = v1 / (1.f + __expf(-v1));
                C[(long)n * M + m1]       = v2 / (1.f + __expf(-v2));
                C[(long)(n + 1) * M + m1] = v3 / (1.f + __expf(-v3));
            }
        }
    }
}

// ---------------------------------------------------------------------------
// Flash attention, tf32 tensor cores.
// Grid: (64 q-tiles, 8 heads). 128 threads = 4 warps; warp w owns 16 q rows.
// KV tile = 64 keys. Ks stride 76 (S-phase reads), Vs stride 72 (PV reads) —
// both conflict-free for their read shapes. P aliases Ks (stride 68).
// ---------------------------------------------------------------------------
#define KSTRIDE 76
#define VSTRIDE 72
#define PSTRIDE 68
#define KTILE 64

__global__ void __launch_bounds__(128, 3) flash_tc_kernel(
    const float* __restrict__ qkv, float* __restrict__ attn_out)
{
    __shared__ __align__(16) uint32_t Ks[KTILE * KSTRIDE];   // aliased as P
    __shared__ __align__(16) uint32_t Vs[KTILE * VSTRIDE];

    const int tid  = threadIdx.x;
    const int w    = tid >> 5;
    const int lane = tid & 31;
    const int g    = lane >> 2;
    const int t    = lane & 3;
    const int h    = blockIdx.y;
    const int q0   = blockIdx.x * 64;
    const float scale = rsqrtf((float)DH);

    // Q fragments: rows q0+w*16+{g, g+8}, 9 k-steps
    uint32_t qa[9][4];
    {
        const float* qb = qkv + (long)(q0 + w * 16) * QKVD + h * DH;
#pragma unroll
        for (int ks = 0; ks < 9; ks++) {
            qa[ks][0] = f2tf32(qb[(long)g       * QKVD + ks * 8 + t]     * scale);
            qa[ks][1] = f2tf32(qb[(long)(g + 8) * QKVD + ks * 8 + t]     * scale);
            qa[ks][2] = f2tf32(qb[(long)g       * QKVD + ks * 8 + t + 4] * scale);
            qa[ks][3] = f2tf32(qb[(long)(g + 8) * QKVD + ks * 8 + t + 4] * scale);
        }
    }

    float o[9][4];
#pragma unroll
    for (int n = 0; n < 9; n++)
#pragma unroll
        for (int j = 0; j < 4; j++) o[n][j] = 0.f;
    float m0 = -1e30f, m1 = -1e30f, l0 = 0.f, l1 = 0.f;

    uint32_t* Pw = Ks + w * (16 * PSTRIDE);

    for (int kt = 0; kt < L_TOK / KTILE; kt++) {
        __syncthreads();

        // stage K,V tiles (tf32-converted, vectorized stores)
        {
            const float* kb = qkv + (long)(kt * KTILE) * QKVD + DIMC + h * DH;
#pragma unroll
            for (int it = 0; it < 9; it++) {
                int idx = tid + it * 128;           // 0..1151
                int row = idx / 18, c = idx % 18;
                const float* src = kb + (long)row * QKVD + c * 4;
                float4 kv = *(const float4*)src;
                *(uint4*)&Ks[row * KSTRIDE + c * 4] =
                    make_uint4(f2tf32(kv.x), f2tf32(kv.y), f2tf32(kv.z), f2tf32(kv.w));
                float4 vv = *(const float4*)(src + DIMC);
                *(uint4*)&Vs[row * VSTRIDE + c * 4] =
                    make_uint4(f2tf32(vv.x), f2tf32(vv.y), f2tf32(vv.z), f2tf32(vv.w));
            }
        }
        __syncthreads();

        // --- S = Q @ K^T  (16 x 64 per warp) ---
        float s[8][4];
#pragma unroll
        for (int n = 0; n < 8; n++)
#pragma unroll
            for (int j = 0; j < 4; j++) s[n][j] = 0.f;

#pragma unroll
        for (int ks = 0; ks < 9; ks++) {
#pragma unroll
            for (int nn = 0; nn < 8; nn++) {
                uint32_t b0 = Ks[(nn * 8 + g) * KSTRIDE + ks * 8 + t];
                uint32_t b1 = Ks[(nn * 8 + g) * KSTRIDE + ks * 8 + t + 4];
                mma_tf32(s[nn], qa[ks], b0, b1);
            }
        }

        // --- online softmax ---
        float rmax0 = -1e30f, rmax1 = -1e30f;
#pragma unroll
        for (int nn = 0; nn < 8; nn++) {
            rmax0 = fmaxf(rmax0, fmaxf(s[nn][0], s[nn][1]));
            rmax1 = fmaxf(rmax1, fmaxf(s[nn][2], s[nn][3]));
        }
        rmax0 = fmaxf(rmax0, __shfl_xor_sync(0xffffffffu, rmax0, 1));
        rmax0 = fmaxf(rmax0, __shfl_xor_sync(0xffffffffu, rmax0, 2));
        rmax1 = fmaxf(rmax1, __shfl_xor_sync(0xffffffffu, rmax1, 1));
        rmax1 = fmaxf(rmax1, __shfl_xor_sync(0xffffffffu, rmax1, 2));

        float mn0 = fmaxf(m0, rmax0), mn1 = fmaxf(m1, rmax1);
        float corr0 = __expf(m0 - mn0), corr1 = __expf(m1 - mn1);
        m0 = mn0; m1 = mn1;

        __syncthreads();   // Ks reads done -> safe to overwrite with P

        float rs0 = 0.f, rs1 = 0.f;
#pragma unroll
        for (int nn = 0; nn < 8; nn++) {
            float p0 = __expf(s[nn][0] - mn0);
            float p1 = __expf(s[nn][1] - mn0);
            float p2 = __expf(s[nn][2] - mn1);
            float p3 = __expf(s[nn][3] - mn1);
            rs0 += p0 + p1; rs1 += p2 + p3;
            *(uint2*)&Pw[g       * PSTRIDE + nn * 8 + 2 * t] =
                make_uint2(f2tf32(p0), f2tf32(p1));
            *(uint2*)&Pw[(g + 8) * PSTRIDE + nn * 8 + 2 * t] =
                make_uint2(f2tf32(p2), f2tf32(p3));
        }
        rs0 += __shfl_xor_sync(0xffffffffu, rs0, 1);
        rs0 += __shfl_xor_sync(0xffffffffu, rs0, 2);
        rs1 += __shfl_xor_sync(0xffffffffu, rs1, 1);
        rs1 += __shfl_xor_sync(0xffffffffu, rs1, 2);
        l0 = l0 * corr0 + rs0;
        l1 = l1 * corr1 + rs1;

#pragma unroll
        for (int n = 0; n < 9; n++) {
            o[n][0] *= corr0; o[n][1] *= corr0;
            o[n][2] *= corr1; o[n][3] *= corr1;
        }

        __syncwarp();

        // --- O += P @ V  (16 x 72 per warp) ---
#pragma unroll
        for (int kk = 0; kk < 8; kk++) {
            uint32_t a[4];
            a[0] = Pw[g       * PSTRIDE + kk * 8 + t];
            a[1] = Pw[(g + 8) * PSTRIDE + kk * 8 + t];
            a[2] = Pw[g       * PSTRIDE + kk * 8 + t + 4];
            a[3] = Pw[(g + 8) * PSTRIDE + kk * 8 + t + 4];
#pragma unroll
            for (int nn = 0; nn < 9; nn++) {
                uint32_t b0 = Vs[(kk * 8 + t)     * VSTRIDE + nn * 8 + g];
                uint32_t b1 = Vs[(kk * 8 + t + 4) * VSTRIDE + nn * 8 + g];
                mma_tf32(o[nn], a, b0, b1);
            }
        }
    }

    // epilogue
    float inv0 = 1.f / l0, inv1 = 1.f / l1;
    float* ob = attn_out + (long)(q0 + w * 16) * DIMC + h * DH;
#pragma unroll
    for (int nn = 0; nn < 9; nn++) {
        *(float2*)(ob + (long)g       * DIMC + nn * 8 + 2 * t) =
            make_float2(o[nn][0] * inv0, o[nn][1] * inv0);
        *(float2*)(ob + (long)(g + 8) * DIMC + nn * 8 + 2 * t) =
            make_float2(o[nn][2] * inv1, o[nn][3] * inv1);
    }
}

// ---------------------------------------------------------------------------
extern "C" void kernel_launch(void* const* d_in, const int* in_sizes, int n_in,
                              void* d_out, int out_size)
{
    const float* fea    = (const float*)d_in[0];
    const float* w_qkv  = (const float*)d_in[1];
    const float* b_qkv  = (const float*)d_in[2];
    const float* w_out  = (const float*)d_in[3];
    const float* b_out  = (const float*)d_in[4];
    const float* conv_w = (const float*)d_in[5];
    float* out = (float*)d_out;

    float* x    = nullptr; cudaGetSymbolAddress((void**)&x,    g_x);
    float* qkv  = nullptr; cudaGetSymbolAddress((void**)&qkv,  g_qkv);
    float* attn = nullptr; cudaGetSymbolAddress((void**)&attn, g_attn);
    float* x2   = nullptr; cudaGetSymbolAddress((void**)&x2,   g_x2);

    // 1) unfold
    unfold_kernel<<<(L_TOK * DIMC + 255) / 256, 256>>>(fea, x);

    // 2) qkv = x @ w_qkv + b_qkv
    tf32_gemm_kernel<0, false><<<dim3(QKVD / 64, L_TOK / 128), 256>>>(
        x, w_qkv, b_qkv, nullptr, qkv, L_TOK, QKVD, DIMC);

    // 3) flash attention (tf32 tensor cores)
    flash_tc_kernel<<<dim3(L_TOK / 64, NHEADS), 128>>>(qkv, attn);

    // 4) x2 = attn @ w_out + b_out + x
    tf32_gemm_kernel<1, false><<<dim3(DIMC / 64, L_TOK / 128), 256>>>(
        attn, w_out, b_out, x, x2, L_TOK, DIMC, DIMC);

    // 5) out[oc,l] = silu( x2 @ conv_w^T )
    tf32_gemm_kernel<2, true><<<dim3(OUTC / 64, L_TOK / 128), 256>>>(
        x2, conv_w, nullptr, nullptr, out, L_TOK, OUTC, DIMC);
}

// round 4
// speedup vs baseline: 3.5698x; 1.0606x over previous
#include <cuda_runtime.h>
#include <cuda_bf16.h>
#include <cstdint>

#define L_TOK 4096
#define DIMC 576
#define QKVD 1728
#define NHEADS 8
#define DH 72
#define OUTC 128

// Scratch (allocation-free: __device__ globals)
__device__ float g_x[L_TOK * DIMC];      // unfold output  [L,576]
__device__ float g_qkv[L_TOK * QKVD];    // qkv            [L,1728]
__device__ float g_attn[L_TOK * DIMC];   // attention out  [L,576]
__device__ float g_x2[L_TOK * DIMC];     // attn+resid     [L,576]

// ---------------------------------------------------------------------------
// helpers
// ---------------------------------------------------------------------------
__device__ __forceinline__ uint32_t f2tf32(float x) {
    uint32_t r;
    asm("cvt.rna.tf32.f32 %0, %1;" : "=r"(r) : "f"(x));
    return r;
}

__device__ __forceinline__ void mma_tf32(float d[4],
                                         const uint32_t a[4],
                                         uint32_t b0, uint32_t b1) {
    asm volatile(
        "mma.sync.aligned.m16n8k8.row.col.f32.tf32.tf32.f32 "
        "{%0,%1,%2,%3}, {%4,%5,%6,%7}, {%8,%9}, {%0,%1,%2,%3};\n"
        : "+f"(d[0]), "+f"(d[1]), "+f"(d[2]), "+f"(d[3])
        : "r"(a[0]), "r"(a[1]), "r"(a[2]), "r"(a[3]), "r"(b0), "r"(b1));
}

__device__ __forceinline__ void cp16(uint32_t smem_addr, const void* gptr) {
    asm volatile("cp.async.cg.shared.global [%0], [%1], 16;\n"
                 :: "r"(smem_addr), "l"(gptr));
}
#define CP_COMMIT() asm volatile("cp.async.commit_group;\n" ::: "memory")
#define CP_WAIT0()  asm volatile("cp.async.wait_group 0;\n" ::: "memory")

// ---------------------------------------------------------------------------
// Unfold 3x3 stride2 pad1
// ---------------------------------------------------------------------------
__global__ void unfold_kernel(const float* __restrict__ fea, float* __restrict__ x) {
    int idx = blockIdx.x * blockDim.x + threadIdx.x;
    if (idx >= L_TOK * DIMC) return;
    int l = idx / DIMC, d = idx - l * DIMC;
    int c = d / 9, r = d - c * 9;
    int ki = r / 3, kj = r - ki * 3;
    int ho = l >> 6, wo = l & 63;
    int h = 2 * ho + ki - 1;
    int w = 2 * wo + kj - 1;
    float v = 0.f;
    if (h >= 0 && h < 128 && w >= 0 && w < 128)
        v = fea[c * 16384 + h * 128 + w];
    x[idx] = v;
}

// ---------------------------------------------------------------------------
// Pipelined tf32 GEMM (MODE 0: +bias, MODE 1: +bias+resid), no transpose.
// BM=128 BN=64 BK=16, 256 threads = 8 warps (4m x 2n), warp tile 32x32.
// cp.async double-buffered staging of raw fp32; cvt.rna at fragment load.
// As stride 20, Bs stride 72 (conflict-free fragment reads).
// ---------------------------------------------------------------------------
#define AST 20
#define BST 72

template <int MODE>
__global__ void __launch_bounds__(256) tf32_gemm_pipe(
    const float* __restrict__ A, const float* __restrict__ B,
    const float* __restrict__ bias, const float* __restrict__ resid,
    float* __restrict__ C, int M, int N, int K)
{
    __shared__ __align__(16) float As[2][128 * AST];
    __shared__ __align__(16) float Bs[2][16 * BST];

    const int tid  = threadIdx.x;
    const int lane = tid & 31;
    const int warp = tid >> 5;
    const int g = lane >> 2;
    const int t = lane & 3;
    const int wm = (warp >> 1) * 32;
    const int wn = (warp & 1) * 32;
    const int bm = blockIdx.y * 128;
    const int bn = blockIdx.x * 64;

    // staging maps
    const int a_row0 = (tid * 2) >> 2;         // chunks tid*2, tid*2+1
    const int a_c0   = (tid * 2) & 3;
    const int a_row1 = (tid * 2 + 1) >> 2;
    const int a_c1   = (tid * 2 + 1) & 3;
    const int b_row  = tid >> 4;
    const int b_c    = tid & 15;

    auto stage = [&](int k0, int buf) {
        cp16(__cvta_generic_to_shared(&As[buf][a_row0 * AST + a_c0 * 4]),
             A + (long)(bm + a_row0) * K + k0 + a_c0 * 4);
        cp16(__cvta_generic_to_shared(&As[buf][a_row1 * AST + a_c1 * 4]),
             A + (long)(bm + a_row1) * K + k0 + a_c1 * 4);
        cp16(__cvta_generic_to_shared(&Bs[buf][b_row * BST + b_c * 4]),
             B + (long)(k0 + b_row) * N + bn + b_c * 4);
    };

    float acc[2][4][4];
#pragma unroll
    for (int i = 0; i < 2; i++)
#pragma unroll
        for (int j = 0; j < 4; j++)
#pragma unroll
            for (int f = 0; f < 4; f++) acc[i][j][f] = 0.f;

    const int ns = K / 16;
    stage(0, 0);
    CP_COMMIT();

    for (int kt = 0; kt < ns; kt++) {
        CP_WAIT0();
        __syncthreads();
        if (kt + 1 < ns) {
            stage((kt + 1) * 16, (kt + 1) & 1);
            CP_COMMIT();
        }
        const float* Ab = As[kt & 1];
        const float* Bb = Bs[kt & 1];
#pragma unroll
        for (int ks = 0; ks < 2; ks++) {
            uint32_t af[2][4];
#pragma unroll
            for (int i = 0; i < 2; i++) {
                int mb = wm + i * 16;
                af[i][0] = f2tf32(Ab[(mb + g)     * AST + ks * 8 + t]);
                af[i][1] = f2tf32(Ab[(mb + g + 8) * AST + ks * 8 + t]);
                af[i][2] = f2tf32(Ab[(mb + g)     * AST + ks * 8 + t + 4]);
                af[i][3] = f2tf32(Ab[(mb + g + 8) * AST + ks * 8 + t + 4]);
            }
#pragma unroll
            for (int j = 0; j < 4; j++) {
                uint32_t b0 = f2tf32(Bb[(ks * 8 + t)     * BST + wn + j * 8 + g]);
                uint32_t b1 = f2tf32(Bb[(ks * 8 + t + 4) * BST + wn + j * 8 + g]);
                mma_tf32(acc[0][j], af[0], b0, b1);
                mma_tf32(acc[1][j], af[1], b0, b1);
            }
        }
    }

    // epilogue
#pragma unroll
    for (int i = 0; i < 2; i++) {
#pragma unroll
        for (int j = 0; j < 4; j++) {
            int m0 = bm + wm + i * 16 + g;
            int m1 = m0 + 8;
            int n  = bn + wn + j * 8 + 2 * t;
            float2 bb = *(const float2*)(bias + n);
            if (MODE == 0) {
                *(float2*)(C + (long)m0 * N + n) =
                    make_float2(acc[i][j][0] + bb.x, acc[i][j][1] + bb.y);
                *(float2*)(C + (long)m1 * N + n) =
                    make_float2(acc[i][j][2] + bb.x, acc[i][j][3] + bb.y);
            } else {
                float2 r0 = *(const float2*)(resid + (long)m0 * N + n);
                float2 r1 = *(const float2*)(resid + (long)m1 * N + n);
                *(float2*)(C + (long)m0 * N + n) =
                    make_float2(acc[i][j][0] + bb.x + r0.x, acc[i][j][1] + bb.y + r0.y);
                *(float2*)(C + (long)m1 * N + n) =
                    make_float2(acc[i][j][2] + bb.x + r1.x, acc[i][j][3] + bb.y + r1.y);
            }
        }
    }
}

// ---------------------------------------------------------------------------
// Final GEMM (TRANSB, silu, transposed store) — R3 style, small (12us)
// ---------------------------------------------------------------------------
__global__ void __launch_bounds__(256) tf32_gemm_final(
    const float* __restrict__ A, const float* __restrict__ B,
    float* __restrict__ C, int M, int N, int K)
{
    __shared__ __align__(16) uint32_t As[128 * AST];
    __shared__ __align__(16) uint32_t Bs[16 * BST];

    const int tid  = threadIdx.x;
    const int lane = tid & 31;
    const int warp = tid >> 5;
    const int g = lane >> 2;
    const int t = lane & 3;
    const int wm = (warp >> 1) * 32;
    const int wn = (warp & 1) * 32;
    const int bm = blockIdx.y * 128;
    const int bn = blockIdx.x * 64;

    const int a_m = tid >> 1;
    const int a_k = (tid & 1) * 8;
    const int b_n = tid >> 2;
    const int b_k = (tid & 3) * 4;

    float acc[2][4][4];
#pragma unroll
    for (int i = 0; i < 2; i++)
#pragma unroll
        for (int j = 0; j < 4; j++)
#pragma unroll
            for (int f = 0; f < 4; f++) acc[i][j][f] = 0.f;

    for (int k0 = 0; k0 < K; k0 += 16) {
        {
            const float* Ap = A + (long)(bm + a_m) * K + k0 + a_k;
            float4 v0 = *(const float4*)(Ap);
            float4 v1 = *(const float4*)(Ap + 4);
            *(uint4*)&As[a_m * AST + a_k] =
                make_uint4(f2tf32(v0.x), f2tf32(v0.y), f2tf32(v0.z), f2tf32(v0.w));
            *(uint4*)&As[a_m * AST + a_k + 4] =
                make_uint4(f2tf32(v1.x), f2tf32(v1.y), f2tf32(v1.z), f2tf32(v1.w));
        }
        {
            float4 bv = *(const float4*)(B + (long)(bn + b_n) * K + k0 + b_k);
            Bs[(b_k + 0) * BST + b_n] = f2tf32(bv.x);
            Bs[(b_k + 1) * BST + b_n] = f2tf32(bv.y);
            Bs[(b_k + 2) * BST + b_n] = f2tf32(bv.z);
            Bs[(b_k + 3) * BST + b_n] = f2tf32(bv.w);
        }
        __syncthreads();

#pragma unroll
        for (int ks = 0; ks < 2; ks++) {
            uint32_t af[2][4];
#pragma unroll
            for (int i = 0; i < 2; i++) {
                int mb = wm + i * 16;
                af[i][0] = As[(mb + g)     * AST + ks * 8 + t];
                af[i][1] = As[(mb + g + 8) * AST + ks * 8 + t];
                af[i][2] = As[(mb + g)     * AST + ks * 8 + t + 4];
                af[i][3] = As[(mb + g + 8) * AST + ks * 8 + t + 4];
            }
#pragma unroll
            for (int j = 0; j < 4; j++) {
                uint32_t b0 = Bs[(ks * 8 + t)     * BST + wn + j * 8 + g];
                uint32_t b1 = Bs[(ks * 8 + t + 4) * BST + wn + j * 8 + g];
                mma_tf32(acc[0][j], af[0], b0, b1);
                mma_tf32(acc[1][j], af[1], b0, b1);
            }
        }
        __syncthreads();
    }

#pragma unroll
    for (int i = 0; i < 2; i++) {
#pragma unroll
        for (int j = 0; j < 4; j++) {
            int m0 = bm + wm + i * 16 + g;
            int m1 = m0 + 8;
            int n  = bn + wn + j * 8 + 2 * t;
            float v0 = acc[i][j][0], v1 = acc[i][j][1];
            float v2 = acc[i][j][2], v3 = acc[i][j][3];
            C[(long)n * M + m0]       = v0 / (1.f + __expf(-v0));
            C[(long)(n + 1) * M + m0] = v1 / (1.f + __expf(-v1));
            C[(long)n * M + m1]       = v2 / (1.f + __expf(-v2));
            C[(long)(n + 1) * M + m1] = v3 / (1.f + __expf(-v3));
        }
    }
}

// ---------------------------------------------------------------------------
// Flash attention, tf32 tensor cores, cp.async double-buffered K/V.
// Grid: (32 q-tiles of 128, 8 heads). 256 threads = 8 warps x 16 q-rows.
// KV tile = 32 keys, 128 tiles. P stays in registers: c-frag -> a-frag via
// shuffles. Ks stride 76, Vs stride 72 (conflict-free fragment reads).
// ---------------------------------------------------------------------------
#define KSTRIDE 76
#define VSTRIDE 72
#define KT32 32

__global__ void __launch_bounds__(256, 2) flash_tc_kernel(
    const float* __restrict__ qkv, float* __restrict__ attn_out)
{
    __shared__ __align__(16) float Ksm[2][KT32 * KSTRIDE];
    __shared__ __align__(16) float Vsm[2][KT32 * VSTRIDE];

    const int tid  = threadIdx.x;
    const int w    = tid >> 5;
    const int lane = tid & 31;
    const int g    = lane >> 2;
    const int t    = lane & 3;
    const int h    = blockIdx.y;
    const int q0   = blockIdx.x * 128;
    const float scale = rsqrtf((float)DH);
    const unsigned FULL = 0xffffffffu;
    const int src1 = (lane & ~3) | (t >> 1);
    const int src2 = src1 + 2;
    const bool odd = (t & 1);

    // staging lambda: K and V chunks for tile kt into buffer buf
    auto stage = [&](int kt, int buf) {
        const float* base = qkv + (long)(kt * KT32) * QKVD + DIMC + h * DH;
#pragma unroll
        for (int i = 0; i < 3; i++) {
            int idx = tid + i * 256;
            if (idx < 576) {
                int row = idx / 18, c = idx % 18;
                cp16(__cvta_generic_to_shared(&Ksm[buf][row * KSTRIDE + c * 4]),
                     base + (long)row * QKVD + c * 4);
            }
        }
#pragma unroll
        for (int i = 0; i < 3; i++) {
            int idx = tid + i * 256;
            if (idx < 576) {
                int row = idx / 18, c = idx % 18;
                cp16(__cvta_generic_to_shared(&Vsm[buf][row * VSTRIDE + c * 4]),
                     base + DIMC + (long)row * QKVD + c * 4);
            }
        }
    };

    // Q fragments: rows q0+w*16+{g,g+8}, 9 k-steps
    uint32_t qa[9][4];
    {
        const float* qb = qkv + (long)(q0 + w * 16) * QKVD + h * DH;
#pragma unroll
        for (int ks = 0; ks < 9; ks++) {
            qa[ks][0] = f2tf32(qb[(long)g       * QKVD + ks * 8 + t]     * scale);
            qa[ks][1] = f2tf32(qb[(long)(g + 8) * QKVD + ks * 8 + t]     * scale);
            qa[ks][2] = f2tf32(qb[(long)g       * QKVD + ks * 8 + t + 4] * scale);
            qa[ks][3] = f2tf32(qb[(long)(g + 8) * QKVD + ks * 8 + t + 4] * scale);
        }
    }

    float o[9][4];
#pragma unroll
    for (int n = 0; n < 9; n++)
#pragma unroll
        for (int j = 0; j < 4; j++) o[n][j] = 0.f;
    float m0 = -1e30f, m1 = -1e30f, l0 = 0.f, l1 = 0.f;

    stage(0, 0);
    CP_COMMIT();

    const int NT = L_TOK / KT32;  // 128
    for (int kt = 0; kt < NT; kt++) {
        CP_WAIT0();
        __syncthreads();
        if (kt + 1 < NT) {
            stage(kt + 1, (kt + 1) & 1);
            CP_COMMIT();
        }
        const float* Kb = Ksm[kt & 1];
        const float* Vb = Vsm[kt & 1];

        // --- S = Q @ K^T (16 x 32 per warp) ---
        float s[4][4];
#pragma unroll
        for (int n = 0; n < 4; n++)
#pragma unroll
            for (int j = 0; j < 4; j++) s[n][j] = 0.f;

#pragma unroll
        for (int ks = 0; ks < 9; ks++) {
#pragma unroll
            for (int nn = 0; nn < 4; nn++) {
                uint32_t b0 = f2tf32(Kb[(nn * 8 + g) * KSTRIDE + ks * 8 + t]);
                uint32_t b1 = f2tf32(Kb[(nn * 8 + g) * KSTRIDE + ks * 8 + t + 4]);
                mma_tf32(s[nn], qa[ks], b0, b1);
            }
        }

        // --- online softmax ---
        float rmax0 = -1e30f, rmax1 = -1e30f;
#pragma unroll
        for (int nn = 0; nn < 4; nn++) {
            rmax0 = fmaxf(rmax0, fmaxf(s[nn][0], s[nn][1]));
            rmax1 = fmaxf(rmax1, fmaxf(s[nn][2], s[nn][3]));
        }
        rmax0 = fmaxf(rmax0, __shfl_xor_sync(FULL, rmax0, 1));
        rmax0 = fmaxf(rmax0, __shfl_xor_sync(FULL, rmax0, 2));
        rmax1 = fmaxf(rmax1, __shfl_xor_sync(FULL, rmax1, 1));
        rmax1 = fmaxf(rmax1, __shfl_xor_sync(FULL, rmax1, 2));

        float mn0 = fmaxf(m0, rmax0), mn1 = fmaxf(m1, rmax1);
        float corr0 = __expf(m0 - mn0), corr1 = __expf(m1 - mn1);
        m0 = mn0; m1 = mn1;

        float rs0 = 0.f, rs1 = 0.f;
#pragma unroll
        for (int nn = 0; nn < 4; nn++) {
            float p0 = __expf(s[nn][0] - mn0);
            float p1 = __expf(s[nn][1] - mn0);
            float p2 = __expf(s[nn][2] - mn1);
            float p3 = __expf(s[nn][3] - mn1);
            rs0 += p0 + p1; rs1 += p2 + p3;
            // store tf32-rounded P back into s (bit pattern as float)
            s[nn][0] = __uint_as_float(f2tf32(p0));
            s[nn][1] = __uint_as_float(f2tf32(p1));
            s[nn][2] = __uint_as_float(f2tf32(p2));
            s[nn][3] = __uint_as_float(f2tf32(p3));
        }
        rs0 += __shfl_xor_sync(FULL, rs0, 1);
        rs0 += __shfl_xor_sync(FULL, rs0, 2);
        rs1 += __shfl_xor_sync(FULL, rs1, 1);
        rs1 += __shfl_xor_sync(FULL, rs1, 2);
        l0 = l0 * corr0 + rs0;
        l1 = l1 * corr1 + rs1;

#pragma unroll
        for (int n = 0; n < 9; n++) {
            o[n][0] *= corr0; o[n][1] *= corr0;
            o[n][2] *= corr1; o[n][3] *= corr1;
        }

        // --- O += P @ V (16 x 72 per warp); P a-frags via shuffles ---
#pragma unroll
        for (int kk = 0; kk < 4; kk++) {
            // row g (regs 0,1), row g+8 (regs 2,3); c-layout cols {2t,2t+1}
            float x0 = __shfl_sync(FULL, s[kk][0], src1);
            float x1 = __shfl_sync(FULL, s[kk][1], src1);
            float a0f = odd ? x1 : x0;              // P[g][t]
            float y0 = __shfl_sync(FULL, s[kk][0], src2);
            float y1 = __shfl_sync(FULL, s[kk][1], src2);
            float a2f = odd ? y1 : y0;              // P[g][t+4]
            float x2 = __shfl_sync(FULL, s[kk][2], src1);
            float x3 = __shfl_sync(FULL, s[kk][3], src1);
            float a1f = odd ? x3 : x2;              // P[g+8][t]
            float y2 = __shfl_sync(FULL, s[kk][2], src2);
            float y3 = __shfl_sync(FULL, s[kk][3], src2);
            float a3f = odd ? y3 : y2;              // P[g+8][t+4]
            uint32_t a[4] = {__float_as_uint(a0f), __float_as_uint(a1f),
                             __float_as_uint(a2f), __float_as_uint(a3f)};
#pragma unroll
            for (int nn = 0; nn < 9; nn++) {
                uint32_t b0 = f2tf32(Vb[(kk * 8 + t)     * VSTRIDE + nn * 8 + g]);
                uint32_t b1 = f2tf32(Vb[(kk * 8 + t + 4) * VSTRIDE + nn * 8 + g]);
                mma_tf32(o[nn], a, b0, b1);
            }
        }
    }

    // epilogue
    float inv0 = 1.f / l0, inv1 = 1.f / l1;
    float* ob = attn_out + (long)(q0 + w * 16) * DIMC + h * DH;
#pragma unroll
    for (int nn = 0; nn < 9; nn++) {
        *(float2*)(ob + (long)g       * DIMC + nn * 8 + 2 * t) =
            make_float2(o[nn][0] * inv0, o[nn][1] * inv0);
        *(float2*)(ob + (long)(g + 8) * DIMC + nn * 8 + 2 * t) =
            make_float2(o[nn][2] * inv1, o[nn][3] * inv1);
    }
}

// ---------------------------------------------------------------------------
extern "C" void kernel_launch(void* const* d_in, const int* in_sizes, int n_in,
                              void* d_out, int out_size)
{
    const float* fea    = (const float*)d_in[0];
    const float* w_qkv  = (const float*)d_in[1];
    const float* b_qkv  = (const float*)d_in[2];
    const float* w_out  = (const float*)d_in[3];
    const float* b_out  = (const float*)d_in[4];
    const float* conv_w = (const float*)d_in[5];
    float* out = (float*)d_out;

    float* x    = nullptr; cudaGetSymbolAddress((void**)&x,    g_x);
    float* qkv  = nullptr; cudaGetSymbolAddress((void**)&qkv,  g_qkv);
    float* attn = nullptr; cudaGetSymbolAddress((void**)&attn, g_attn);
    float* x2   = nullptr; cudaGetSymbolAddress((void**)&x2,   g_x2);

    // 1) unfold
    unfold_kernel<<<(L_TOK * DIMC + 255) / 256, 256>>>(fea, x);

    // 2) qkv = x @ w_qkv + b_qkv
    tf32_gemm_pipe<0><<<dim3(QKVD / 64, L_TOK / 128), 256>>>(
        x, w_qkv, b_qkv, nullptr, qkv, L_TOK, QKVD, DIMC);

    // 3) flash attention
    flash_tc_kernel<<<dim3(L_TOK / 128, NHEADS), 256>>>(qkv, attn);

    // 4) x2 = attn @ w_out + b_out + x
    tf32_gemm_pipe<1><<<dim3(DIMC / 64, L_TOK / 128), 256>>>(
        attn, w_out, b_out, x, x2, L_TOK, DIMC, DIMC);

    // 5) out[oc,l] = silu( x2 @ conv_w^T )
    tf32_gemm_final<<<dim3(OUTC / 64, L_TOK / 128), 256>>>(
        x2, conv_w, out, L_TOK, OUTC, DIMC);
}